// round 5
// baseline (speedup 1.0000x reference)
#include <cuda_runtime.h>
#include <cuda_bf16.h>
#include <cstdint>

// Problem constants (fixed by the reference)
#define EMB    64
#define HEADS  8
#define DIMI   20
#define NQ     4116                  // DIMI + 16*16*16
#define ROWF4  1029                  // 4116 / 4
#define TABR   63                    // 2*CAP - 1
#define INVT   0.125f                // 64^-0.5

#define NPROJ  (3 * HEADS * TABR)    // 1512
#define NCROSS (HEADS * DIMI)        // 160
#define NITEMS (NPROJ + NCROSS)      // 1672

#define NROWS  (HEADS * NQ)          // 32928
#define TOTF4  (NROWS * ROWF4)       // 33,886,512 float4s

#define GRID_SCORES 1184             // 148 SMs * 8 CTAs
#define BLK         256

// Precomputed small tables (scaling folded in)
__device__ float g_projH[HEADS * TABR];   // * INVT/3
__device__ float g_projW[HEADS * TABR];
__device__ float g_projD[HEADS * TABR];
__device__ float g_cross[HEADS * DIMI];   // * INVT

// One warp per output scalar: lane c handles elements c and c+32 of the
// 64-length dot product, then butterfly-reduce.
__global__ __launch_bounds__(256)
void prep_kernel(const float* __restrict__ enc_cross,
                 const float* __restrict__ enc_h,
                 const float* __restrict__ enc_w,
                 const float* __restrict__ enc_d,
                 const float* __restrict__ w_cross,
                 const float* __restrict__ w_h,
                 const float* __restrict__ w_w,
                 const float* __restrict__ w_d) {
    const int warp = blockIdx.x * 8 + (threadIdx.x >> 5);
    const int lane = threadIdx.x & 31;
    if (warp >= NITEMS) return;

    const float* vec;
    const float* w;
    float scale;
    float* dst;

    if (warp < NPROJ) {
        const int axis = warp / (HEADS * TABR);
        const int rem  = warp - axis * (HEADS * TABR);
        const int h = rem / TABR, r = rem - h * TABR;
        const float* tab = (axis == 0) ? enc_h : (axis == 1) ? enc_w : enc_d;
        const float* wt  = (axis == 0) ? w_h   : (axis == 1) ? w_w   : w_d;
        float* db        = (axis == 0) ? g_projH : (axis == 1) ? g_projW : g_projD;
        vec = tab + r * EMB;
        w   = wt + h * EMB;
        scale = INVT / 3.0f;
        dst = db + h * TABR + r;
    } else {
        const int rem = warp - NPROJ;
        const int h = rem / DIMI, n = rem - h * DIMI;
        vec = enc_cross + n * EMB;
        w   = w_cross + h * EMB;
        scale = INVT;
        dst = g_cross + h * DIMI + n;
    }

    float s = w[lane] * vec[lane] + w[lane + 32] * vec[lane + 32];
    #pragma unroll
    for (int off = 16; off > 0; off >>= 1)
        s += __shfl_xor_sync(0xffffffffu, s, off);
    if (lane == 0) *dst = s * scale;
}

// Persistent grid-stride kernel: each thread walks the global float4 index
// space with stride gridDim*blockDim. All per-head tables live in smem.
__global__ __launch_bounds__(BLK)
void scores_kernel(float* __restrict__ out) {
    __shared__ float sH[HEADS * TABR];   // 504
    __shared__ float sW[HEADS * TABR];
    __shared__ float sD[HEADS * TABR];
    __shared__ float sC[HEADS * DIMI];   // 160

    const int t = threadIdx.x;
    for (int k = t; k < HEADS * TABR; k += BLK) {
        sH[k] = g_projH[k];
        sW[k] = g_projW[k];
        sD[k] = g_projD[k];
    }
    for (int k = t; k < HEADS * DIMI; k += BLK) sC[k] = g_cross[k];
    __syncthreads();

    float4* __restrict__ dst = reinterpret_cast<float4*>(out);
    const int stride = GRID_SCORES * BLK;

    for (int g = blockIdx.x * BLK + t; g < TOTF4; g += stride) {
        const int row = g / ROWF4;          // mulhi sequence
        const int f   = g - row * ROWF4;
        const int h   = row / NQ;           // mulhi sequence
        const int q   = row - h * NQ;

        float4 v;
        if (q < DIMI) {
            v = make_float4(0.f, 0.f, 0.f, 0.f);
        } else if (f < 5) {
            const float* c = &sC[h * DIMI + 4 * f];
            v.x = c[0]; v.y = c[1]; v.z = c[2]; v.w = c[3];
        } else {
            const int s  = q - DIMI;
            const int i  = s >> 8;
            const int j  = (s >> 4) & 15;
            const int k3 = s & 15;
            const int scol = 4 * f - DIMI;  // multiple of 4
            const int l  = scol >> 8;
            const int m  = (scol >> 4) & 15;
            const int n0 = scol & 15;
            const float base = sH[h * TABR + l - i + 31] + sW[h * TABR + m - j + 31];
            const float* d = &sD[h * TABR + n0 - k3 + 31];
            v.x = base + d[0];
            v.y = base + d[1];
            v.z = base + d[2];
            v.w = base + d[3];
        }
        dst[g] = v;
    }
}

extern "C" void kernel_launch(void* const* d_in, const int* in_sizes, int n_in,
                              void* d_out, int out_size) {
    const float* enc_cross = (const float*)d_in[0];
    const float* enc_h     = (const float*)d_in[1];
    const float* enc_w     = (const float*)d_in[2];
    const float* enc_d     = (const float*)d_in[3];
    const float* w_cross   = (const float*)d_in[4];
    const float* w_h       = (const float*)d_in[5];
    const float* w_w       = (const float*)d_in[6];
    const float* w_d       = (const float*)d_in[7];
    float* out = (float*)d_out;

    prep_kernel<<<(NITEMS + 7) / 8, 256>>>(enc_cross, enc_h, enc_w, enc_d,
                                           w_cross, w_h, w_w, w_d);
    scores_kernel<<<GRID_SCORES, BLK>>>(out);
}

// round 7
// speedup vs baseline: 1.1461x; 1.1461x over previous
#include <cuda_runtime.h>
#include <cuda_bf16.h>
#include <cstdint>

// Problem constants (fixed by the reference)
#define EMB    64
#define HEADS  8
#define DIMI   20
#define NQ     4116                  // DIMI + 16*16*16
#define ROWF4  1029                  // 4116 / 4
#define TABR   63                    // 2*CAP - 1
#define INVT   0.125f                // 64^-0.5

#define NPROJ  (3 * HEADS * TABR)    // 1512
#define NCROSS (HEADS * DIMI)        // 160
#define NITEMS (NPROJ + NCROSS)      // 1672

#define CONTENT_BLOCKS 8192          // HEADS*16*16*4  (h, i, j, k3 group of 4)
#define ZERO_BLOCKS    40            // 160 zero rows / 4
#define GRID_SCORES    (CONTENT_BLOCKS + ZERO_BLOCKS)
#define SPAN_F4        (4 * ROWF4)   // 4116 float4 per block

// Precomputed small tables (scaling folded in)
__device__ float g_projH[HEADS * TABR];   // * INVT/3
__device__ float g_projW[HEADS * TABR];
__device__ float g_projD[HEADS * TABR];
__device__ float g_cross[HEADS * DIMI];   // * INVT

// One warp per output scalar: lane c handles elements c and c+32 of the
// 64-length dot product, then butterfly-reduce.
__global__ __launch_bounds__(256)
void prep_kernel(const float* __restrict__ enc_cross,
                 const float* __restrict__ enc_h,
                 const float* __restrict__ enc_w,
                 const float* __restrict__ enc_d,
                 const float* __restrict__ w_cross,
                 const float* __restrict__ w_h,
                 const float* __restrict__ w_w,
                 const float* __restrict__ w_d) {
    const int warp = blockIdx.x * 8 + (threadIdx.x >> 5);
    const int lane = threadIdx.x & 31;
    if (warp >= NITEMS) return;

    const float* vec;
    const float* w;
    float scale;
    float* dst;

    if (warp < NPROJ) {
        const int axis = warp / (HEADS * TABR);
        const int rem  = warp - axis * (HEADS * TABR);
        const int h = rem / TABR, r = rem - h * TABR;
        const float* tab = (axis == 0) ? enc_h : (axis == 1) ? enc_w : enc_d;
        const float* wt  = (axis == 0) ? w_h   : (axis == 1) ? w_w   : w_d;
        float* db        = (axis == 0) ? g_projH : (axis == 1) ? g_projW : g_projD;
        vec = tab + r * EMB;
        w   = wt + h * EMB;
        scale = INVT / 3.0f;
        dst = db + h * TABR + r;
    } else {
        const int rem = warp - NPROJ;
        const int h = rem / DIMI, n = rem - h * DIMI;
        vec = enc_cross + n * EMB;
        w   = w_cross + h * EMB;
        scale = INVT;
        dst = g_cross + h * DIMI + n;
    }

    float s = w[lane] * vec[lane] + w[lane + 32] * vec[lane + 32];
    #pragma unroll
    for (int off = 16; off > 0; off >>= 1)
        s += __shfl_xor_sync(0xffffffffu, s, off);
    if (lane == 0) *dst = s * scale;
}

// Content block: (h, i, j, k3-group) -> 4 consecutive rows, contiguous 65.9 KB.
// Zero block: 4 consecutive all-zero rows of one head.
__global__ __launch_bounds__(256)
void scores_kernel(float* __restrict__ out) {
    const int b = blockIdx.x;
    const int t = threadIdx.x;

    if (b >= CONTENT_BLOCKS) {
        const int zb = b - CONTENT_BLOCKS;        // 0..39
        const int h  = zb / 5;                    // 4-row groups stay in one head
        const int q0 = (zb - h * 5) * 4;
        float4* __restrict__ dst =
            reinterpret_cast<float4*>(out + ((size_t)h * NQ + q0) * NQ);
        const float4 z = make_float4(0.f, 0.f, 0.f, 0.f);
        #pragma unroll 4
        for (int g = t; g < SPAN_F4; g += 256) dst[g] = z;
        return;
    }

    const int h  = b >> 10;
    const int i  = (b >> 6) & 15;
    const int j  = (b >> 2) & 15;
    const int kg = b & 3;                         // k3 = 4*kg + r, r = 0..3

    __shared__ float sa[16], sb[16], sd[4][16], scr[DIMI];
    // sa[l], sb[m]: pre-shifted by i/j.  sd[r][n0]: pre-shifted by k3 of row r.
    if (t < 16)             sa[t]      = g_projH[h * TABR + t - i + 31];
    else if (t < 32)        sb[t - 16] = g_projW[h * TABR + (t - 16) - j + 31];
    else if (t < 96) {
        const int r  = (t - 32) >> 4;
        const int n0 = (t - 32) & 15;
        sd[r][n0] = g_projD[h * TABR + n0 - (4 * kg + r) + 31];
    }
    else if (t < 96 + DIMI) scr[t - 96] = g_cross[h * DIMI + (t - 96)];
    __syncthreads();

    const int base_row = h * NQ + DIMI + i * 256 + j * 16 + 4 * kg;
    float4* __restrict__ dst = reinterpret_cast<float4*>(out + (size_t)base_row * NQ);

    #pragma unroll 4
    for (int g = t; g < SPAN_F4; g += 256) {
        const int r = g / ROWF4;          // 0..3, mulhi sequence
        const int f = g - r * ROWF4;
        float4 v;
        if (f < 5) {
            const float* c = &scr[4 * f];
            v.x = c[0]; v.y = c[1]; v.z = c[2]; v.w = c[3];
        } else {
            const int scol = 4 * f - DIMI;         // multiple of 4
            const int l  = scol >> 8;
            const int m  = (scol >> 4) & 15;
            const int n0 = scol & 15;
            const float base = sa[l] + sb[m];
            const float* d = &sd[r][n0];
            v.x = base + d[0];
            v.y = base + d[1];
            v.z = base + d[2];
            v.w = base + d[3];
        }
        dst[g] = v;
    }
}

extern "C" void kernel_launch(void* const* d_in, const int* in_sizes, int n_in,
                              void* d_out, int out_size) {
    const float* enc_cross = (const float*)d_in[0];
    const float* enc_h     = (const float*)d_in[1];
    const float* enc_w     = (const float*)d_in[2];
    const float* enc_d     = (const float*)d_in[3];
    const float* w_cross   = (const float*)d_in[4];
    const float* w_h       = (const float*)d_in[5];
    const float* w_w       = (const float*)d_in[6];
    const float* w_d       = (const float*)d_in[7];
    float* out = (float*)d_out;

    prep_kernel<<<(NITEMS + 7) / 8, 256>>>(enc_cross, enc_h, enc_w, enc_d,
                                           w_cross, w_h, w_w, w_d);
    scores_kernel<<<GRID_SCORES, 256>>>(out);
}